// round 1
// baseline (speedup 1.0000x reference)
#include <cuda_runtime.h>

#define C 128
#define PE_DIM 8
#define NG 512
#define MAXN 131072
#define BN_EPS 1e-5f
#define BM 64
#define AS_LD 132   // padded A-tile leading dim (bank-conflict relief)

// ---------------- scratch (device globals; no runtime allocation) ----------------
__device__ float  g_h[(size_t)MAXN * C];
__device__ float  g_agg[(size_t)MAXN * C];
__device__ float  g_lin[(size_t)MAXN * C];
__device__ float  g_deg[MAXN];
__device__ float  g_dinv[MAXN];
__device__ double g_stats[2 * C];          // [0..127] sum, [128..255] sumsq
__device__ float  g_pool[NG * C];
__device__ float  g_cnt[NG];
__device__ float  g_hidden[NG * C];
__device__ int    g_e64, g_b64;            // index dtype flags (1 = int64)

// ---------------- helpers ----------------
__device__ __forceinline__ int ldidx(const void* p, long long i, int is64) {
    if (is64) return (int)((const long long*)p)[i];
    return ((const int*)p)[i];
}

__device__ __forceinline__ void red4(float* p, float a, float b, float c, float d) {
    asm volatile("red.global.add.v4.f32 [%0], {%1,%2,%3,%4};"
                 :: "l"(p), "f"(a), "f"(b), "f"(c), "f"(d) : "memory");
}

// ---------------- dtype detection ----------------
// int64 values here are < 1e5 (upper 32 bits zero). If the buffer is actually
// int32, reading it as u64 words combines adjacent entries -> some sampled word
// has nonzero upper half (edges: random; batch: sorted, later samples have g>=1).
__global__ void k_detect(const void* p, long long elems, int which) {
    if (threadIdx.x || blockIdx.x) return;
    long long half = elems / 2;   // safe word count for both dtypes
    int is64 = 1;
    if (half > 0) {
        const unsigned long long* q = (const unsigned long long*)p;
        for (int i = 0; i < 512; i++) {
            long long pos = (long long)i * (half - 1) / 511;
            if (q[pos] >> 32) { is64 = 0; break; }
        }
    }
    if (which == 0) g_e64 = is64; else g_b64 = is64;
}

// ---------------- degree / dinv ----------------
__global__ void k_zero_deg(int N) {
    int n = blockIdx.x * blockDim.x + threadIdx.x;
    if (n < N) g_deg[n] = 0.0f;
}

__global__ void k_deg(const void* eix, int E) {
    int e = blockIdx.x * blockDim.x + threadIdx.x;
    if (e >= E) return;
    int r = ldidx(eix, e, g_e64);
    atomicAdd(&g_deg[r], 1.0f);
}

__global__ void k_dinv(int N) {
    int n = blockIdx.x * blockDim.x + threadIdx.x;
    if (n >= N) return;
    float d = g_deg[n];
    g_dinv[n] = (d > 0.0f) ? rsqrtf(d) : 0.0f;
}

// ---------------- input projection: h = x@node_W + node_b + pe@pe_W + pe_b ----------------
__global__ void k_input(const float* __restrict__ x, const float* __restrict__ pe,
                        const float* __restrict__ nW, const float* __restrict__ nb,
                        const float* __restrict__ pW, const float* __restrict__ pb, int N) {
    int idx = blockIdx.x * blockDim.x + threadIdx.x;
    if (idx >= N * C) return;
    int n = idx >> 7, c = idx & (C - 1);
    float v = x[n] * nW[c] + nb[c] + pb[c];
#pragma unroll
    for (int k = 0; k < PE_DIM; k++) v += pe[n * PE_DIM + k] * pW[k * C + c];
    g_h[idx] = v;
}

// ---------------- agg = h (scatter then adds on top) ----------------
__global__ void k_copy(int N) {
    int idx = blockIdx.x * blockDim.x + threadIdx.x;
    if (idx < N * 32) ((float4*)g_agg)[idx] = ((const float4*)g_h)[idx];
}

// ---------------- edge scatter: agg[row] += h[col] * dinv[row]*dinv[col] ----------------
// one warp per edge; each lane handles 4 contiguous channels via red.v4
__global__ void k_scatter(const void* eix, int E) {
    long long t = (long long)blockIdx.x * blockDim.x + threadIdx.x;
    if (t >= (long long)E * 32) return;
    int e = (int)(t >> 5);
    int j = (int)(t & 31);
    int is64 = g_e64;
    int r  = ldidx(eix, e, is64);
    int co = ldidx(eix, (long long)E + e, is64);
    float nrm = g_dinv[r] * g_dinv[co];
    float4 v = *(((const float4*)(g_h + (size_t)co * C)) + j);
    red4((float*)(((float4*)(g_agg + (size_t)r * C)) + j),
         v.x * nrm, v.y * nrm, v.z * nrm, v.w * nrm);
}

// ---------------- GEMM: g_lin = g_agg @ W (128x128), bias omitted (cancels in BN) ----------------
__global__ void k_gemm(const float* __restrict__ Wg, int N) {
    extern __shared__ float sm[];
    float* Ws = sm;                 // C*C
    float* As = sm + C * C;         // BM*AS_LD
    int tid = threadIdx.x;          // 256 threads
    for (int i = tid; i < C * C / 4; i += blockDim.x)
        ((float4*)Ws)[i] = ((const float4*)Wg)[i];
    __syncthreads();

    int tx = tid & 15;              // 16 col-groups of 8
    int ty = tid >> 4;              // 16 row-groups of 4
    const float4* WsV = (const float4*)Ws;
    int ntiles = (N + BM - 1) / BM;

    for (int tI = blockIdx.x; tI < ntiles; tI += gridDim.x) {
        int row0 = tI * BM;
        __syncthreads();
        for (int i = tid; i < BM * 32; i += blockDim.x) {
            int r = i >> 5, c4 = i & 31;
            float4 v = make_float4(0.f, 0.f, 0.f, 0.f);
            if (row0 + r < N) v = ((const float4*)(g_agg + (size_t)(row0 + r) * C))[c4];
            *(float4*)(As + r * AS_LD + c4 * 4) = v;
        }
        __syncthreads();

        float acc[4][8];
#pragma unroll
        for (int i = 0; i < 4; i++)
#pragma unroll
            for (int j = 0; j < 8; j++) acc[i][j] = 0.0f;

#pragma unroll 8
        for (int k = 0; k < C; k++) {
            float a[4];
#pragma unroll
            for (int i = 0; i < 4; i++) a[i] = As[(ty * 4 + i) * AS_LD + k];
            float w[8];
            *(float4*)&w[0] = WsV[k * 32 + tx * 2];
            *(float4*)&w[4] = WsV[k * 32 + tx * 2 + 1];
#pragma unroll
            for (int i = 0; i < 4; i++)
#pragma unroll
                for (int j = 0; j < 8; j++) acc[i][j] += a[i] * w[j];
        }

#pragma unroll
        for (int i = 0; i < 4; i++) {
            int r = row0 + ty * 4 + i;
            if (r < N) {
                float4* dst = ((float4*)(g_lin + (size_t)r * C)) + tx * 2;
                dst[0] = make_float4(acc[i][0], acc[i][1], acc[i][2], acc[i][3]);
                dst[1] = make_float4(acc[i][4], acc[i][5], acc[i][6], acc[i][7]);
            }
        }
    }
}

// ---------------- BN stats (fp64 accumulation) ----------------
__global__ void k_zero_stats() {
    int t = threadIdx.x;
    if (t < 2 * C) g_stats[t] = 0.0;
}

__global__ void k_stats(int N) {
    int c = threadIdx.x;            // 128 threads
    double s = 0.0, q = 0.0;
    for (int r = blockIdx.x; r < N; r += gridDim.x) {
        float v = g_lin[(size_t)r * C + c];
        s += v;
        q += (double)v * v;
    }
    atomicAdd(&g_stats[c], s);
    atomicAdd(&g_stats[C + c], q);
}

// ---------------- BN apply + ReLU + residual: h += relu(BN(lin)) ----------------
__global__ void k_apply(const float* __restrict__ gamma, const float* __restrict__ beta, int N) {
    int idx = blockIdx.x * blockDim.x + threadIdx.x;
    if (idx >= N * 32) return;
    int c = (idx & 31) * 4;
    float4 lv = ((const float4*)g_lin)[idx];
    float4 hv = ((float4*)g_h)[idx];
    float l[4] = {lv.x, lv.y, lv.z, lv.w};
    float h[4] = {hv.x, hv.y, hv.z, hv.w};
#pragma unroll
    for (int t = 0; t < 4; t++) {
        double mean = g_stats[c + t] / (double)N;
        double var  = g_stats[C + c + t] / (double)N - mean * mean;
        float inv = rsqrtf((float)var + BN_EPS);
        float val = (float)((double)l[t] - mean) * inv * gamma[c + t] + beta[c + t];
        h[t] += fmaxf(val, 0.0f);
    }
    ((float4*)g_h)[idx] = make_float4(h[0], h[1], h[2], h[3]);
}

// ---------------- mean pooling per graph ----------------
__global__ void k_zero_pool() {
    int idx = blockIdx.x * blockDim.x + threadIdx.x;
    if (idx < NG * C) g_pool[idx] = 0.0f;
    if (idx < NG) g_cnt[idx] = 0.0f;
}

__global__ void k_pool(const void* batch, int N) {
    int idx = blockIdx.x * blockDim.x + threadIdx.x;
    if (idx >= N * 32) return;
    int n = idx >> 5, j = idx & 31;
    int g = ldidx(batch, n, g_b64);
    float4 v = ((const float4*)g_h)[idx];
    red4(&g_pool[g * C + j * 4], v.x, v.y, v.z, v.w);
    if (j == 0) atomicAdd(&g_cnt[g], 1.0f);
}

// ---------------- head: hidden = relu(pooled @ W1 + b1) ----------------
__global__ void k_head1(const float* __restrict__ W1, const float* __restrict__ b1) {
    __shared__ float ps[C];
    int g = blockIdx.x, c = threadIdx.x;
    float cn = fmaxf(g_cnt[g], 1.0f);
    ps[c] = g_pool[g * C + c] / cn;
    __syncthreads();
    float acc = b1[c];
#pragma unroll 8
    for (int k = 0; k < C; k++) acc += ps[k] * W1[k * C + c];
    g_hidden[g * C + c] = fmaxf(acc, 0.0f);
}

// ---------------- head: out = hidden @ W2 + b2 ----------------
__global__ void k_head2(const float* __restrict__ W2, const float* __restrict__ b2,
                        float* __restrict__ out) {
    int t = blockIdx.x * blockDim.x + threadIdx.x;
    int g = t >> 5, lane = t & 31;
    if (g >= NG) return;
    float acc = 0.0f;
#pragma unroll
    for (int j = 0; j < 4; j++) {
        int c = lane + 32 * j;
        acc += g_hidden[g * C + c] * W2[c];
    }
#pragma unroll
    for (int o = 16; o; o >>= 1) acc += __shfl_xor_sync(0xffffffffu, acc, o);
    if (lane == 0) out[g] = acc + b2[0];
}

// ---------------- launch ----------------
extern "C" void kernel_launch(void* const* d_in, const int* in_sizes, int n_in,
                              void* d_out, int out_size) {
    // input slots (num_nodes scalar may or may not occupy slot 4)
    int o = (n_in >= 17) ? 1 : 0;
    const float* x     = (const float*)d_in[0];
    const float* pe    = (const float*)d_in[1];
    const void*  eix   = d_in[2];
    const void*  batch = d_in[3];
    const float* nW    = (const float*)d_in[4 + o];
    const float* nb    = (const float*)d_in[5 + o];
    const float* pW    = (const float*)d_in[6 + o];
    const float* pb    = (const float*)d_in[7 + o];
    const float* convW = (const float*)d_in[8 + o];
    // conv_b (9+o) skipped: cancels exactly under BatchNorm
    const float* gamma = (const float*)d_in[10 + o];
    const float* beta  = (const float*)d_in[11 + o];
    const float* W1    = (const float*)d_in[12 + o];
    const float* b1    = (const float*)d_in[13 + o];
    const float* W2    = (const float*)d_in[14 + o];
    const float* b2    = (const float*)d_in[15 + o];

    int N = in_sizes[0];            // x is (N,1)
    int E = in_sizes[2] / 2;        // edge_index is (2,E)
    if (N > MAXN) N = MAXN;

    const int smem = (C * C + BM * AS_LD) * (int)sizeof(float);   // 99328 B
    cudaFuncSetAttribute(k_gemm, cudaFuncAttributeMaxDynamicSharedMemorySize, smem);

    k_detect<<<1, 32>>>(eix, (long long)in_sizes[2], 0);
    k_detect<<<1, 32>>>(batch, (long long)in_sizes[3], 1);

    k_zero_deg<<<(N + 255) / 256, 256>>>(N);
    k_deg<<<(E + 255) / 256, 256>>>(eix, E);
    k_dinv<<<(N + 255) / 256, 256>>>(N);
    k_input<<<(N * C + 255) / 256, 256>>>(x, pe, nW, nb, pW, pb, N);

    int scatter_blocks = (int)(((long long)E * 32 + 255) / 256);
    for (int l = 0; l < 3; l++) {
        k_copy<<<(N * 32 + 255) / 256, 256>>>(N);
        k_scatter<<<scatter_blocks, 256>>>(eix, E);
        k_gemm<<<296, 256, smem>>>(convW + (size_t)l * C * C, N);
        k_zero_stats<<<1, 256>>>();
        k_stats<<<512, C>>>(N);
        k_apply<<<(N * 32 + 255) / 256, 256>>>(gamma + l * C, beta + l * C, N);
    }

    k_zero_pool<<<(NG * C + 255) / 256, 256>>>();
    k_pool<<<(N * 32 + 255) / 256, 256>>>(batch, N);
    k_head1<<<NG, C>>>(W1, b1);
    k_head2<<<(NG * 32 + 255) / 256, 256>>>(W2, b2, (float*)d_out);
}

// round 2
// speedup vs baseline: 1.7882x; 1.7882x over previous
#include <cuda_runtime.h>

#define C 128
#define PE_DIM 8
#define NG 512
#define MAXN 131072
#define MAXE 2000000
#define BN_EPS 1e-5f
#define BM 64
#define AS_LD 132
#define SB 1024

// ---------------- scratch (device globals) ----------------
__device__ float  g_h[(size_t)MAXN * C];
__device__ float  g_agg[(size_t)MAXN * C];
__device__ float  g_lin[(size_t)MAXN * C];
__device__ int    g_degi[MAXN];
__device__ int    g_cur[MAXN];
__device__ int    g_incl[MAXN];
__device__ int    g_bsum[1024];
__device__ int    g_off[MAXN + 1];
__device__ float  g_dinv[MAXN];
__device__ int2   g_csr[MAXE];            // (col, norm-bits)
__device__ double g_stats[2 * C];         // sum / sumsq
__device__ float  g_bnscale[C], g_bnshift[C];
__device__ float  g_pool[NG * C];
__device__ float  g_cnt[NG];
__device__ float  g_hidden[NG * C];
__device__ int    g_e64, g_b64;

// ---------------- helpers ----------------
__device__ __forceinline__ int ldidx(const void* p, long long i, int is64) {
    if (is64) return (int)((const long long*)p)[i];
    return ((const int*)p)[i];
}

__device__ __forceinline__ void red4(float* p, float a, float b, float c, float d) {
    asm volatile("red.global.add.v4.f32 [%0], {%1,%2,%3,%4};"
                 :: "l"(p), "f"(a), "f"(b), "f"(c), "f"(d) : "memory");
}

// ---------------- index dtype detection ----------------
__global__ void k_detect(const void* p, long long elems, int which) {
    if (threadIdx.x || blockIdx.x) return;
    long long half = elems / 2;
    int is64 = 1;
    if (half > 0) {
        const unsigned long long* q = (const unsigned long long*)p;
        for (int i = 0; i < 512; i++) {
            long long pos = (long long)i * (half - 1) / 511;
            if (q[pos] >> 32) { is64 = 0; break; }
        }
    }
    if (which == 0) g_e64 = is64; else g_b64 = is64;
}

// ---------------- CSR build ----------------
__global__ void k_zero2(int N) {
    int n = blockIdx.x * blockDim.x + threadIdx.x;
    if (n < N) { g_degi[n] = 0; g_cur[n] = 0; }
}

__global__ void k_deg(const void* eix, int E) {
    int e = blockIdx.x * blockDim.x + threadIdx.x;
    if (e >= E) return;
    atomicAdd(&g_degi[ldidx(eix, e, g_e64)], 1);
}

__global__ void k_dinv(int N) {
    int n = blockIdx.x * blockDim.x + threadIdx.x;
    if (n >= N) return;
    int d = g_degi[n];
    g_dinv[n] = (d > 0) ? rsqrtf((float)d) : 0.0f;
}

__global__ void k_scan1(int N) {
    __shared__ int sm[SB];
    int i = blockIdx.x * SB + threadIdx.x;
    int v = (i < N) ? g_degi[i] : 0;
    sm[threadIdx.x] = v; __syncthreads();
    for (int o = 1; o < SB; o <<= 1) {
        int t = (threadIdx.x >= o) ? sm[threadIdx.x - o] : 0;
        __syncthreads();
        sm[threadIdx.x] += t;
        __syncthreads();
    }
    if (i < N) g_incl[i] = sm[threadIdx.x];
    if (threadIdx.x == SB - 1) g_bsum[blockIdx.x] = sm[SB - 1];
}

__global__ void k_scan2(int nb) {
    __shared__ int sm[1024];
    int v = (threadIdx.x < nb) ? g_bsum[threadIdx.x] : 0;
    sm[threadIdx.x] = v; __syncthreads();
    for (int o = 1; o < 1024; o <<= 1) {
        int t = (threadIdx.x >= o) ? sm[threadIdx.x - o] : 0;
        __syncthreads();
        sm[threadIdx.x] += t;
        __syncthreads();
    }
    if (threadIdx.x < nb) g_bsum[threadIdx.x] = sm[threadIdx.x] - v;   // exclusive
}

__global__ void k_scan3(int N) {
    int i = blockIdx.x * blockDim.x + threadIdx.x;
    if (i == 0) g_off[0] = 0;
    if (i < N) g_off[i + 1] = g_incl[i] + g_bsum[i >> 10];
}

__global__ void k_fill(const void* eix, int E) {
    int e = blockIdx.x * blockDim.x + threadIdx.x;
    if (e >= E) return;
    int is64 = g_e64;
    int r = ldidx(eix, e, is64);
    int c = ldidx(eix, (long long)E + e, is64);
    int pos = g_off[r] + atomicAdd(&g_cur[r], 1);
    g_csr[pos] = make_int2(c, __float_as_int(g_dinv[r] * g_dinv[c]));
}

// ---------------- input projection ----------------
__global__ void k_input(const float* __restrict__ x, const float* __restrict__ pe,
                        const float* __restrict__ nW, const float* __restrict__ nb,
                        const float* __restrict__ pW, const float* __restrict__ pb, int N) {
    int idx = blockIdx.x * blockDim.x + threadIdx.x;
    if (idx >= N * C) return;
    int n = idx >> 7, c = idx & (C - 1);
    float v = x[n] * nW[c] + nb[c] + pb[c];
#pragma unroll
    for (int k = 0; k < PE_DIM; k++) v += pe[n * PE_DIM + k] * pW[k * C + c];
    g_h[idx] = v;
}

// ---------------- aggregation: warp per node, CSR gather, no atomics ----------------
__global__ void k_aggr(int N) {
    int w = (blockIdx.x * blockDim.x + threadIdx.x) >> 5;
    int lane = threadIdx.x & 31;
    if (w >= N) return;
    int s = g_off[w], e = g_off[w + 1];
    const float4* hb = (const float4*)g_h;
    float4 acc = make_float4(0.f, 0.f, 0.f, 0.f);
    int i = s;
    for (; i + 1 < e; i += 2) {
        int2 a = g_csr[i];
        int2 b = g_csr[i + 1];
        float4 va = hb[(size_t)a.x * 32 + lane];
        float4 vb = hb[(size_t)b.x * 32 + lane];
        float na = __int_as_float(a.y), nb2 = __int_as_float(b.y);
        acc.x += na * va.x + nb2 * vb.x;
        acc.y += na * va.y + nb2 * vb.y;
        acc.z += na * va.z + nb2 * vb.z;
        acc.w += na * va.w + nb2 * vb.w;
    }
    if (i < e) {
        int2 a = g_csr[i];
        float4 va = hb[(size_t)a.x * 32 + lane];
        float na = __int_as_float(a.y);
        acc.x += na * va.x; acc.y += na * va.y;
        acc.z += na * va.z; acc.w += na * va.w;
    }
    float4 hv = hb[(size_t)w * 32 + lane];
    acc.x += hv.x; acc.y += hv.y; acc.z += hv.z; acc.w += hv.w;
    ((float4*)g_agg)[(size_t)w * 32 + lane] = acc;
}

// ---------------- GEMM + fused BN-stat partials ----------------
__global__ void k_gemm(const float* __restrict__ Wg, int N) {
    extern __shared__ float sm[];
    float* Ws = sm;                 // C*C floats
    float* As = sm + C * C;         // BM*AS_LD floats (also reused for stat reduction)
    int tid = threadIdx.x;          // 256 threads
    for (int i = tid; i < C * C / 4; i += blockDim.x)
        ((float4*)Ws)[i] = ((const float4*)Wg)[i];
    __syncthreads();

    int tx = tid & 15;              // 16 col-groups of 8 channels
    int ty = tid >> 4;              // 16 row-groups of 4 rows
    const float4* WsV = (const float4*)Ws;
    int ntiles = (N + BM - 1) / BM;

    for (int tI = blockIdx.x; tI < ntiles; tI += gridDim.x) {
        int row0 = tI * BM;
        __syncthreads();
        for (int i = tid; i < BM * 32; i += blockDim.x) {
            int r = i >> 5, c4 = i & 31;
            float4 v = make_float4(0.f, 0.f, 0.f, 0.f);
            if (row0 + r < N) v = ((const float4*)(g_agg + (size_t)(row0 + r) * C))[c4];
            *(float4*)(As + r * AS_LD + c4 * 4) = v;
        }
        __syncthreads();

        float acc[4][8];
#pragma unroll
        for (int i = 0; i < 4; i++)
#pragma unroll
            for (int j = 0; j < 8; j++) acc[i][j] = 0.0f;

#pragma unroll 8
        for (int k = 0; k < C; k++) {
            float a[4];
#pragma unroll
            for (int i = 0; i < 4; i++) a[i] = As[(ty * 4 + i) * AS_LD + k];
            float w[8];
            *(float4*)&w[0] = WsV[k * 32 + tx * 2];
            *(float4*)&w[4] = WsV[k * 32 + tx * 2 + 1];
#pragma unroll
            for (int i = 0; i < 4; i++)
#pragma unroll
                for (int j = 0; j < 8; j++) acc[i][j] += a[i] * w[j];
        }

        // write output tile
#pragma unroll
        for (int i = 0; i < 4; i++) {
            int r = row0 + ty * 4 + i;
            if (r < N) {
                float4* dst = ((float4*)(g_lin + (size_t)r * C)) + tx * 2;
                dst[0] = make_float4(acc[i][0], acc[i][1], acc[i][2], acc[i][3]);
                dst[1] = make_float4(acc[i][4], acc[i][5], acc[i][6], acc[i][7]);
            }
        }

        // fused BN stats: per-column partial sums over this 64-row tile.
        // Padding rows have acc==0 (As zero-filled) -> contribute nothing.
        float s[8], q[8];
#pragma unroll
        for (int j = 0; j < 8; j++) {
            s[j] = acc[0][j] + acc[1][j] + acc[2][j] + acc[3][j];
            q[j] = acc[0][j] * acc[0][j] + acc[1][j] * acc[1][j]
                 + acc[2][j] * acc[2][j] + acc[3][j] * acc[3][j];
        }
        __syncthreads();                       // everyone done reading As
#pragma unroll
        for (int j = 0; j < 8; j++) {
            As[ty * C + tx * 8 + j]        = s[j];
            As[2048 + ty * C + tx * 8 + j] = q[j];
        }
        __syncthreads();
        if (tid < C) {
            float ss = 0.f, qq = 0.f;
#pragma unroll
            for (int t = 0; t < 16; t++) {
                ss += As[t * C + tid];
                qq += As[2048 + t * C + tid];
            }
            atomicAdd(&g_stats[tid], (double)ss);
            atomicAdd(&g_stats[C + tid], (double)qq);
        }
    }
}

// ---------------- BN finalize (once per layer) ----------------
__global__ void k_zero_stats() {
    int t = threadIdx.x;
    if (t < 2 * C) g_stats[t] = 0.0;
}

__global__ void k_bnfin(const float* __restrict__ gamma, const float* __restrict__ beta, int N) {
    int c = threadIdx.x;    // 128
    double mean = g_stats[c] / (double)N;
    double var  = g_stats[C + c] / (double)N - mean * mean;
    float inv = rsqrtf((float)var + BN_EPS);
    float sc = gamma[c] * inv;
    g_bnscale[c] = sc;
    g_bnshift[c] = beta[c] - (float)mean * sc;
}

// ---------------- BN apply + ReLU + residual ----------------
__global__ void k_apply(int N) {
    int idx = blockIdx.x * blockDim.x + threadIdx.x;
    if (idx >= N * 32) return;
    int c = (idx & 31) * 4;
    float4 lv = ((const float4*)g_lin)[idx];
    float4 hv = ((float4*)g_h)[idx];
    hv.x += fmaxf(lv.x * g_bnscale[c + 0] + g_bnshift[c + 0], 0.0f);
    hv.y += fmaxf(lv.y * g_bnscale[c + 1] + g_bnshift[c + 1], 0.0f);
    hv.z += fmaxf(lv.z * g_bnscale[c + 2] + g_bnshift[c + 2], 0.0f);
    hv.w += fmaxf(lv.w * g_bnscale[c + 3] + g_bnshift[c + 3], 0.0f);
    ((float4*)g_h)[idx] = hv;
}

// ---------------- pooling ----------------
__global__ void k_zero_pool() {
    int idx = blockIdx.x * blockDim.x + threadIdx.x;
    if (idx < NG * C) g_pool[idx] = 0.0f;
    if (idx < NG) g_cnt[idx] = 0.0f;
}

__global__ void k_pool(const void* batch, int N) {
    int idx = blockIdx.x * blockDim.x + threadIdx.x;
    if (idx >= N * 32) return;
    int n = idx >> 5, j = idx & 31;
    int g = ldidx(batch, n, g_b64);
    float4 v = ((const float4*)g_h)[idx];
    red4(&g_pool[g * C + j * 4], v.x, v.y, v.z, v.w);
    if (j == 0) atomicAdd(&g_cnt[g], 1.0f);
}

// ---------------- head ----------------
__global__ void k_head1(const float* __restrict__ W1, const float* __restrict__ b1) {
    __shared__ float ps[C];
    int g = blockIdx.x, c = threadIdx.x;
    float cn = fmaxf(g_cnt[g], 1.0f);
    ps[c] = g_pool[g * C + c] / cn;
    __syncthreads();
    float acc = b1[c];
#pragma unroll 8
    for (int k = 0; k < C; k++) acc += ps[k] * W1[k * C + c];
    g_hidden[g * C + c] = fmaxf(acc, 0.0f);
}

__global__ void k_head2(const float* __restrict__ W2, const float* __restrict__ b2,
                        float* __restrict__ out) {
    int t = blockIdx.x * blockDim.x + threadIdx.x;
    int g = t >> 5, lane = t & 31;
    if (g >= NG) return;
    float acc = 0.0f;
#pragma unroll
    for (int j = 0; j < 4; j++) acc += g_hidden[g * C + lane + 32 * j] * W2[lane + 32 * j];
#pragma unroll
    for (int o = 16; o; o >>= 1) acc += __shfl_xor_sync(0xffffffffu, acc, o);
    if (lane == 0) out[g] = acc + b2[0];
}

// ---------------- launch ----------------
extern "C" void kernel_launch(void* const* d_in, const int* in_sizes, int n_in,
                              void* d_out, int out_size) {
    int o = (n_in >= 17) ? 1 : 0;
    const float* x     = (const float*)d_in[0];
    const float* pe    = (const float*)d_in[1];
    const void*  eix   = d_in[2];
    const void*  batch = d_in[3];
    const float* nW    = (const float*)d_in[4 + o];
    const float* nb    = (const float*)d_in[5 + o];
    const float* pW    = (const float*)d_in[6 + o];
    const float* pb    = (const float*)d_in[7 + o];
    const float* convW = (const float*)d_in[8 + o];
    const float* gamma = (const float*)d_in[10 + o];
    const float* beta  = (const float*)d_in[11 + o];
    const float* W1    = (const float*)d_in[12 + o];
    const float* b1    = (const float*)d_in[13 + o];
    const float* W2    = (const float*)d_in[14 + o];
    const float* b2    = (const float*)d_in[15 + o];

    int N = in_sizes[0];
    int E = in_sizes[2] / 2;
    if (N > MAXN) N = MAXN;
    if (E > MAXE) E = MAXE;

    const int smem = (C * C + BM * AS_LD) * (int)sizeof(float);
    cudaFuncSetAttribute(k_gemm, cudaFuncAttributeMaxDynamicSharedMemorySize, smem);

    k_detect<<<1, 32>>>(eix, (long long)in_sizes[2], 0);
    k_detect<<<1, 32>>>(batch, (long long)in_sizes[3], 1);

    // CSR build
    int nb2 = (N + SB - 1) / SB;
    k_zero2<<<(N + 255) / 256, 256>>>(N);
    k_deg<<<(E + 255) / 256, 256>>>(eix, E);
    k_dinv<<<(N + 255) / 256, 256>>>(N);
    k_scan1<<<nb2, SB>>>(N);
    k_scan2<<<1, 1024>>>(nb2);
    k_scan3<<<(N + 255) / 256, 256>>>(N);
    k_fill<<<(E + 255) / 256, 256>>>(eix, E);

    k_input<<<(N * C + 255) / 256, 256>>>(x, pe, nW, nb, pW, pb, N);

    int aggr_blocks = (N * 32 + 255) / 256;
    for (int l = 0; l < 3; l++) {
        k_aggr<<<aggr_blocks, 256>>>(N);
        k_zero_stats<<<1, 256>>>();
        k_gemm<<<296, 256, smem>>>(convW + (size_t)l * C * C, N);
        k_bnfin<<<1, C>>>(gamma + l * C, beta + l * C, N);
        k_apply<<<(N * 32 + 255) / 256, 256>>>(N);
    }

    k_zero_pool<<<(NG * C + 255) / 256, 256>>>();
    k_pool<<<(N * 32 + 255) / 256, 256>>>(batch, N);
    k_head1<<<NG, C>>>(W1, b1);
    k_head2<<<(NG * 32 + 255) / 256, 256>>>(W2, b2, (float*)d_out);
}